// round 7
// baseline (speedup 1.0000x reference)
#include <cuda_runtime.h>
#include <cuda_bf16.h>

// Dims: B=64, T=64, D=32, H=128, W=256, L=64, K_SUB=2
typedef unsigned uint;

// ---------------- device scratch ----------------
__device__ float4 g_wihq[ 9 * 384];            // GRU input weights fp32 packed
__device__ float4 g_whhq[32 * 384];            // GRU hidden weights fp32 packed
// MLP weight tiles for ldmatrix: 16x16 bf16 tiles, row stride 48B (24 ushorts, 16 used)
__device__ unsigned short g_w0t[144 * 384];    // (256,144): 16 m-tiles x 9 k-tiles
__device__ unsigned short g_w2t[128 * 384];    // (128,256): 8 m-tiles x 16 k-tiles
// w1 A-fragments, per-thread: 16 k-tiles x 4 regs
__device__ uint4 g_w1f[512 * 16];

__device__ __forceinline__ uint pk_bf2(float a, float b) {
    uint lo = (uint)__bfloat16_as_ushort(__float2bfloat16_rn(a));
    uint hi = (uint)__bfloat16_as_ushort(__float2bfloat16_rn(b));
    return (hi << 16) | lo;
}

__global__ void prep_kernel(const float* __restrict__ w0, const float* __restrict__ w1,
                            const float* __restrict__ w2, const float* __restrict__ wih,
                            const float* __restrict__ whh)
{
    int i0 = blockIdx.x * blockDim.x + threadIdx.x;
    int stride = gridDim.x * blockDim.x;

    // w0 tiles: tile = mt*9+kt; element (r,c) at tile*384 + r*24 + c (c<16 valid)
    // K index 0 -> col0 (t_hi), 1..128 -> h, 129 -> col0 again (t_lo), else 0
    for (int idx = i0; idx < 144 * 384; idx += stride) {
        int tile = idx / 384, e = idx % 384, r = e / 24, c = e % 24;
        float v = 0.f;
        if (c < 16) {
            int mt = tile / 9, kt = tile % 9;
            int R = 16 * mt + r, K = 16 * kt + c;
            if (K < 129)       v = w0[R * 129 + K];
            else if (K == 129) v = w0[R * 129];
        }
        g_w0t[idx] = __bfloat16_as_ushort(__float2bfloat16_rn(v));
    }
    // w2 tiles: tile = mt*16+kt
    for (int idx = i0; idx < 128 * 384; idx += stride) {
        int tile = idx / 384, e = idx % 384, r = e / 24, c = e % 24;
        float v = 0.f;
        if (c < 16) {
            int mt = tile >> 4, kt = tile & 15;
            int R = 16 * mt + r, K = 16 * kt + c;
            v = w2[R * 256 + K];
        }
        g_w2t[idx] = __bfloat16_as_ushort(__float2bfloat16_rn(v));
    }
    // w1 fragments: idx = t*64 + kt*4 + i
    for (int idx = i0; idx < 512 * 64; idx += stride) {
        int t = idx >> 6, rem = idx & 63, kt = rem >> 2, i = rem & 3;
        int wid = t >> 5, lane = t & 31, g = lane >> 2, tig = lane & 3;
        int R = 16 * wid + g + ((i & 1) ? 8 : 0);
        int K = 16 * kt + 2 * tig + ((i & 2) ? 8 : 0);
        ((uint*)g_w1f)[idx] = pk_bf2(w1[R * 256 + K], w1[R * 256 + K + 1]);
    }
    // GRU fp32 packs
    for (int idx = i0; idx < 9 * 384; idx += stride) {
        int k4 = idx / 384, j = idx % 384, k = 4 * k4;
        float4 v;
        v.x = (k + 0 < 33) ? wih[j * 33 + k + 0] : 0.f;
        v.y = (k + 1 < 33) ? wih[j * 33 + k + 1] : 0.f;
        v.z = (k + 2 < 33) ? wih[j * 33 + k + 2] : 0.f;
        v.w = (k + 3 < 33) ? wih[j * 33 + k + 3] : 0.f;
        g_wihq[idx] = v;
    }
    for (int idx = i0; idx < 32 * 384; idx += stride) {
        int k4 = idx / 384, j = idx % 384, k = 4 * k4;
        g_whhq[idx] = make_float4(whh[j * 128 + k], whh[j * 128 + k + 1],
                                  whh[j * 128 + k + 2], whh[j * 128 + k + 3]);
    }
}

// ---------------- helpers ----------------
__device__ __forceinline__ uint smem_u32(const void* p) {
    return (uint)__cvta_generic_to_shared(p);
}
__device__ __forceinline__ void ldsm4(uint& r0, uint& r1, uint& r2, uint& r3, uint addr) {
    asm volatile("ldmatrix.sync.aligned.m8n8.x4.shared.b16 {%0,%1,%2,%3}, [%4];"
                 : "=r"(r0), "=r"(r1), "=r"(r2), "=r"(r3) : "r"(addr));
}
__device__ __forceinline__ void ldsmT4(uint& r0, uint& r1, uint& r2, uint& r3, uint addr) {
    asm volatile("ldmatrix.sync.aligned.m8n8.x4.trans.shared.b16 {%0,%1,%2,%3}, [%4];"
                 : "=r"(r0), "=r"(r1), "=r"(r2), "=r"(r3) : "r"(addr));
}
__device__ __forceinline__ void ldsmT2(uint& r0, uint& r1, uint addr) {
    asm volatile("ldmatrix.sync.aligned.m8n8.x2.trans.shared.b16 {%0,%1}, [%2];"
                 : "=r"(r0), "=r"(r1) : "r"(addr));
}
__device__ __forceinline__ void mma16816(float& d0, float& d1, float& d2, float& d3,
                                         uint a0, uint a1, uint a2, uint a3,
                                         uint b0, uint b1) {
    asm volatile("mma.sync.aligned.m16n8k16.row.col.f32.bf16.bf16.f32 "
                 "{%0,%1,%2,%3}, {%4,%5,%6,%7}, {%8,%9}, {%0,%1,%2,%3};"
                 : "+f"(d0), "+f"(d1), "+f"(d2), "+f"(d3)
                 : "r"(a0), "r"(a1), "r"(a2), "r"(a3), "r"(b0), "r"(b1));
}
__device__ __forceinline__ float tanh_fast(float x) {
    float y; asm("tanh.approx.f32 %0, %1;" : "=f"(y) : "f"(x)); return y;
}
__device__ __forceinline__ float softplus_fast(float x) {
    return fmaxf(x, 0.f) + __logf(1.f + __expf(-fabsf(x)));
}
__device__ __forceinline__ float sigmoid_fast(float x) { return 1.f / (1.f + __expf(-x)); }
__device__ __forceinline__ float sigmoidp(float x) { return 1.f / (1.f + expf(-x)); }
__device__ __forceinline__ uint4 rep_bf(float v) {
    uint p = pk_bf2(v, v);
    return make_uint4(p, p, p, p);
}

// dynamic smem: phase 1 = whh fp32 (196608B); phase 2 = w0 tiles (110592B) + w2 tiles (98304B)
#define DYN_SMEM_BYTES 208896
#define W2_SMEM_OFF    110592

__global__ void __launch_bounds__(512, 1)
solve_kernel(const float* __restrict__ ts, const float* __restrict__ ys,
             const float* __restrict__ scale,
             const float* __restrict__ mlp_b0, const float* __restrict__ mlp_b1,
             const float* __restrict__ mlp_b2,
             const float* __restrict__ gru_b, const float* __restrict__ gru_bn,
             const float* __restrict__ htl_w, const float* __restrict__ htl_b,
             const float* __restrict__ htb_w, const float* __restrict__ htb_b,
             const float* __restrict__ lti_w, const float* __restrict__ lti_b,
             const float* __restrict__ lth_w, const float* __restrict__ lth_b,
             float* __restrict__ out)
{
    const int b   = blockIdx.x;
    const int tid = threadIdx.x;
    const int lane = tid & 31, wid = tid >> 5;
    const int g = lane >> 2, tig = lane & 3;

    extern __shared__ __align__(16) char s_dyn[];

    __shared__ __align__(16) float s_xg[36];
    __shared__ __align__(16) float s_hid[128];
    __shared__ float s_ih[384], s_hh[384];
    __shared__ __align__(16) float s_y[136];
    __shared__ __align__(16) float s_tmp[136];
    __shared__ __align__(16) float s_k[6][136];
    // replicated bf16 rows: 16B per element (8 copies) for ldmatrix B operands
    __shared__ __align__(16) uint4 s_xbr[144];   // [t_hi, h(128), t_lo, zeros(130..143)]
    __shared__ __align__(16) uint4 s_a0r[256];
    __shared__ __align__(16) uint4 s_a1r[256];
    __shared__ float s_p[256];                   // layer2 split-K partials
    __shared__ float s_z0[64];
    __shared__ float s_beta;

    const int OFF_H = 64 * 64 * 5;
    const int OFF_Z = OFF_H + 64 * 64 * 128;

    // ---- phase 1: whh into smem ----
    float4* s_whh = (float4*)s_dyn;
    for (int i = tid; i < 32 * 384; i += 512) s_whh[i] = g_whhq[i];

    const float gb  = (tid < 384) ? gru_b[tid]  : 0.f;
    const float gbn = (tid < 128) ? gru_bn[tid] : 0.f;

    if (tid < 128) s_hid[tid] = 0.f;
    if (tid >= 33 && tid < 36) s_xg[tid] = 0.f;
    __syncthreads();

    // ---------------- GRU over reversed sequence ----------------
    for (int step = 0; step < 64; ++step) {
        int r = 63 - step;
        if (tid == 0) s_xg[0] = ts[b * 64 + r];
        if (tid >= 1 && tid < 33) s_xg[tid] = ys[(b * 64 + r) * 32 + (tid - 1)];
        __syncthreads();

        if (tid < 384) {
            const float4* xg4 = (const float4*)s_xg;
            const float4* h4  = (const float4*)s_hid;
            int row = tid;
            float a0 = gb, a1 = 0.f;
            #pragma unroll
            for (int k = 0; k < 9; ++k) {
                float4 w = g_wihq[k * 384 + row];
                float4 x = xg4[k];
                a0 = fmaf(w.x, x.x, fmaf(w.z, x.z, a0));
                a1 = fmaf(w.y, x.y, fmaf(w.w, x.w, a1));
            }
            float c0 = 0.f, c1 = 0.f;
            #pragma unroll 8
            for (int k = 0; k < 32; ++k) {
                float4 w = s_whh[k * 384 + row];
                float4 x = h4[k];
                c0 = fmaf(w.x, x.x, fmaf(w.z, x.z, c0));
                c1 = fmaf(w.y, x.y, fmaf(w.w, x.w, c1));
            }
            s_ih[row] = a0 + a1;
            s_hh[row] = c0 + c1;
        }
        __syncthreads();
        if (tid < 128) {
            float rr = sigmoidp(s_ih[tid] + s_hh[tid]);
            float zz = sigmoidp(s_ih[128 + tid] + s_hh[128 + tid]);
            float nn = tanhf(s_ih[256 + tid] + rr * (s_hh[256 + tid] + gbn));
            s_hid[tid] = nn + zz * (s_hid[tid] - nn);
        }
        __syncthreads();
    }

    // ---------------- head ----------------
    if (tid < 64) {
        float acc = htl_b[tid];
        #pragma unroll 8
        for (int k = 0; k < 128; ++k) acc = fmaf(htl_w[tid * 128 + k], s_hid[k], acc);
        s_z0[tid] = acc;
        out[OFF_Z + b * 64 + tid] = acc;
    }
    __syncthreads();
    if (tid < 128) {
        float acc = lth_b[tid];
        #pragma unroll 8
        for (int k = 0; k < 64; ++k) acc = fmaf(lth_w[tid * 64 + k], s_z0[k], acc);
        s_y[5 + tid] = acc;
    }
    if (tid == 0) {
        float lg[5], mx = -1e30f;
        #pragma unroll
        for (int m = 0; m < 5; ++m) {
            float acc = lti_b[m];
            for (int k = 0; k < 64; ++k) acc = fmaf(lti_w[m * 64 + k], s_z0[k], acc);
            lg[m] = acc; mx = fmaxf(mx, acc);
        }
        float sum = 0.f;
        #pragma unroll
        for (int m = 0; m < 5; ++m) { float e = expf(lg[m] - mx); s_y[m] = e; sum += e; }
        #pragma unroll
        for (int m = 0; m < 5; ++m) s_y[m] /= sum;
    }
    __syncthreads();   // done with s_whh; s_y ready

    // ---- phase 2: MLP weight tiles into smem ----
    {
        uint4* dst0 = (uint4*)s_dyn;
        const uint4* src0 = (const uint4*)g_w0t;
        for (int i = tid; i < 144 * 384 / 8; i += 512) dst0[i] = src0[i];
        uint4* dst2 = (uint4*)(s_dyn + W2_SMEM_OFF);
        const uint4* src2 = (const uint4*)g_w2t;
        for (int i = tid; i < 128 * 384 / 8; i += 512) dst2[i] = src2[i];
    }

    // w1 fragments into registers
    uint4 w1f[16];
    #pragma unroll
    for (int j = 0; j < 16; ++j) w1f[j] = g_w1f[tid * 16 + j];

    // per-thread constants
    const int rowg = 16 * wid + g;
    const float b0lo = mlp_b0[rowg], b0hi = mlp_b0[rowg + 8];
    const float b1lo = mlp_b1[rowg], b1hi = mlp_b1[rowg + 8];
    const float bias2r = (tid >= 5 && tid < 133) ? mlp_b2[tid - 5] : 0.f;
    const float scl = scale[0];

    float hw0 = 0.f, hw1 = 0.f, hw2 = 0.f, hw3 = 0.f, htbb = 0.f;
    if (wid == 15) {
        hw0 = htb_w[lane]; hw1 = htb_w[lane + 32];
        hw2 = htb_w[lane + 64]; hw3 = htb_w[lane + 96];
        htbb = htb_b[0];
    }

    const uint laneoff = (uint)((lane & 15) * 48 + (lane >> 4) * 16);
    const uint w0base = smem_u32(s_dyn) + (uint)(wid * 9 * 768) + laneoff;
    const uint w2base = smem_u32(s_dyn) + W2_SMEM_OFF
                      + (uint)(((wid & 7) * 16 + (wid >> 3) * 8) * 768) + laneoff;
    const int l2row = 16 * (wid & 7) + g;
    const int l2kh  = wid >> 3;

    // B operand base addresses (replicated rows, 16B each)
    const uint xbrA  = smem_u32(s_xbr)  + (uint)(lane * 16);
    const uint xbrT  = smem_u32(s_xbr)  + (uint)(128 * 16 + (lane & 15) * 16);
    const uint a0rA  = smem_u32(s_a0r)  + (uint)(lane * 16);
    const uint a1rA  = smem_u32(s_a1r)  + (uint)((l2kh * 128 + lane) * 16);

    // init s_xbr from initial state; t=0; zero pad rows
    if (tid < 128) s_xbr[1 + tid] = rep_bf(s_y[5 + tid]);
    if (tid == 256) { s_xbr[0] = make_uint4(0,0,0,0); s_xbr[129] = make_uint4(0,0,0,0); }
    if (tid >= 130 && tid < 144) s_xbr[tid] = make_uint4(0,0,0,0);
    __syncthreads();

    // ---------------- vf (s_xbr + yv ready on entry; leaves s_p, s_beta ready) ----------
    auto vf = [&](const float* yv) {
        // layer 0: 9 k-tiles; B via ldmatrix.trans on replicated rows
        {
            float acc[4][4] = {};
            #pragma unroll
            for (int j = 0; j < 4; ++j) {
                uint aA0, aA1, aA2, aA3, aB0, aB1, aB2, aB3, b0, b1, b2, b3;
                ldsm4(aA0, aA1, aA2, aA3, w0base + (uint)((2 * j) * 768));
                ldsm4(aB0, aB1, aB2, aB3, w0base + (uint)((2 * j + 1) * 768));
                ldsmT4(b0, b1, b2, b3, xbrA + (uint)(j * 512));
                mma16816(acc[(2*j)&3][0],   acc[(2*j)&3][1],   acc[(2*j)&3][2],   acc[(2*j)&3][3],
                         aA0, aA1, aA2, aA3, b0, b1);
                mma16816(acc[(2*j+1)&3][0], acc[(2*j+1)&3][1], acc[(2*j+1)&3][2], acc[(2*j+1)&3][3],
                         aB0, aB1, aB2, aB3, b2, b3);
            }
            {
                uint a0_, a1_, a2_, a3_, b0, b1;
                ldsm4(a0_, a1_, a2_, a3_, w0base + (uint)(8 * 768));
                ldsmT2(b0, b1, xbrT);
                mma16816(acc[0][0], acc[0][1], acc[0][2], acc[0][3], a0_, a1_, a2_, a3_, b0, b1);
            }
            float d0 = (acc[0][0] + acc[1][0]) + (acc[2][0] + acc[3][0]);
            float d2 = (acc[0][2] + acc[1][2]) + (acc[2][2] + acc[3][2]);
            if (tig == 0) {
                s_a0r[rowg]     = rep_bf(softplus_fast(d0 + b0lo));
                s_a0r[rowg + 8] = rep_bf(softplus_fast(d2 + b0hi));
            }
        }
        // beta on warp 15 (reads fp32 state)
        if (wid == 15) {
            float p = fmaf(hw0, yv[5 + lane],
                      fmaf(hw1, yv[37 + lane],
                      fmaf(hw2, yv[69 + lane], hw3 * yv[101 + lane])));
            #pragma unroll
            for (int o = 16; o > 0; o >>= 1) p += __shfl_xor_sync(0xffffffffu, p, o);
            if (lane == 0) s_beta = sigmoid_fast(0.01f * (p + htbb));
        }
        __syncthreads();

        // layer 1: 16 k-tiles; A fragments in registers, B via ldmatrix.trans
        {
            float acc[4][4] = {};
            #pragma unroll
            for (int j = 0; j < 8; ++j) {
                uint b0, b1, b2, b3;
                ldsmT4(b0, b1, b2, b3, a0rA + (uint)(j * 512));
                mma16816(acc[(2*j)&3][0],   acc[(2*j)&3][1],   acc[(2*j)&3][2],   acc[(2*j)&3][3],
                         w1f[2*j].x, w1f[2*j].y, w1f[2*j].z, w1f[2*j].w, b0, b1);
                mma16816(acc[(2*j+1)&3][0], acc[(2*j+1)&3][1], acc[(2*j+1)&3][2], acc[(2*j+1)&3][3],
                         w1f[2*j+1].x, w1f[2*j+1].y, w1f[2*j+1].z, w1f[2*j+1].w, b2, b3);
            }
            float d0 = (acc[0][0] + acc[1][0]) + (acc[2][0] + acc[3][0]);
            float d2 = (acc[0][2] + acc[1][2]) + (acc[2][2] + acc[3][2]);
            if (tig == 0) {
                s_a1r[rowg]     = rep_bf(softplus_fast(d0 + b1lo));
                s_a1r[rowg + 8] = rep_bf(softplus_fast(d2 + b1hi));
            }
        }
        __syncthreads();

        // layer 2: split-K over warp pairs (8 k-tiles each); partials to s_p
        {
            float acc[4][4] = {};
            #pragma unroll
            for (int j = 0; j < 4; ++j) {
                uint aA0, aA1, aA2, aA3, aB0, aB1, aB2, aB3, b0, b1, b2, b3;
                ldsm4(aA0, aA1, aA2, aA3, w2base + (uint)((2 * j) * 768));
                ldsm4(aB0, aB1, aB2, aB3, w2base + (uint)((2 * j + 1) * 768));
                ldsmT4(b0, b1, b2, b3, a1rA + (uint)(j * 512));
                mma16816(acc[(2*j)&3][0],   acc[(2*j)&3][1],   acc[(2*j)&3][2],   acc[(2*j)&3][3],
                         aA0, aA1, aA2, aA3, b0, b1);
                mma16816(acc[(2*j+1)&3][0], acc[(2*j+1)&3][1], acc[(2*j+1)&3][2], acc[(2*j+1)&3][3],
                         aB0, aB1, aB2, aB3, b2, b3);
            }
            float d0 = (acc[0][0] + acc[1][0]) + (acc[2][0] + acc[3][0]);
            float d2 = (acc[0][2] + acc[1][2]) + (acc[2][2] + acc[3][2]);
            if (tig == 0) {
                s_p[l2kh * 128 + l2row]     = d0;
                s_p[l2kh * 128 + l2row + 8] = d2;
            }
        }
        __syncthreads();
    };

    // new k for this thread (combine phase)
    auto knew = [&](const float* yv) -> float {
        if (tid >= 5) {
            float z = s_p[tid - 5] + s_p[tid + 123] + bias2r;
            return scl * (0.1f * tanh_fast(1e-4f * z));
        }
        float S = yv[0], E = yv[1], I = yv[2], A = yv[3];
        float LL = 0.5f * I + A;
        float bSL = s_beta * S * LL;
        if (tid == 0) return -bSL;
        if (tid == 1) return bSL - 0.526f * E;
        if (tid == 2) return fmaf((float)(0.667 * 0.526), E, -(0.244f * I));
        if (tid == 3) return fmaf((float)((1.0 - 0.667) * 0.526), E, -(0.244f * A));
        return fmaf((float)(0.98 * 0.244), I, 0.244f * A);
    };

    auto set_t = [&](float tn) {
        unsigned short u = __bfloat16_as_ushort(__float2bfloat16_rn(tn));
        uint p = ((uint)u << 16) | (uint)u;
        s_xbr[0] = make_uint4(p, p, p, p);
        float thi = __uint_as_float(((uint)u) << 16);
        s_xbr[129] = rep_bf(tn - thi);
    };

    const float C2 = 0.161f, C3 = 0.327f, C4 = 0.9f;
    const float C5 = (float)0.9800255409045097;
    const float A21 = 0.161f;
    const float A31 = (float)-0.008480655492356989, A32 = (float)0.335480655492357;
    const float A41 = (float)2.8971530571054935,  A42 = (float)-6.359448489975075,
                A43 = (float)4.3622954328695815;
    const float A51 = (float)5.325864828439257,   A52 = (float)-11.748883564062828,
                A53 = (float)7.4955393428898365,  A54 = (float)-0.09249506636175525;
    const float A61 = (float)5.86145544294642,    A62 = (float)-12.92096931784711,
                A63 = (float)8.159367898576159,   A64 = (float)-0.071584973281401,
                A65 = (float)-0.028269050394068383;
    const float B1 = (float)0.09646076681806523, B2 = 0.01f,
                B3 = (float)0.4798896504144996,  B4 = (float)1.379008574103742,
                B5 = (float)-3.290069515436081,  B6 = (float)2.324710524099774;

    auto tsit5 = [&](float tt, float h, float t_after) {
        vf(s_y);
        if (tid < 133) {
            float k0 = knew(s_y); s_k[0][tid] = k0;
            float v = s_y[tid] + h * (A21 * k0);
            s_tmp[tid] = v;
            if (tid >= 5) s_xbr[tid - 4] = rep_bf(v);
        }
        if (tid == 256) set_t(tt + C2 * h);
        __syncthreads();

        vf(s_tmp);
        if (tid < 133) {
            float k1 = knew(s_tmp); s_k[1][tid] = k1;
            float v = s_y[tid] + h * (A31 * s_k[0][tid] + A32 * k1);
            s_tmp[tid] = v;
            if (tid >= 5) s_xbr[tid - 4] = rep_bf(v);
        }
        if (tid == 256) set_t(tt + C3 * h);
        __syncthreads();

        vf(s_tmp);
        if (tid < 133) {
            float k2 = knew(s_tmp); s_k[2][tid] = k2;
            float v = s_y[tid] + h * (A41 * s_k[0][tid] + A42 * s_k[1][tid] + A43 * k2);
            s_tmp[tid] = v;
            if (tid >= 5) s_xbr[tid - 4] = rep_bf(v);
        }
        if (tid == 256) set_t(tt + C4 * h);
        __syncthreads();

        vf(s_tmp);
        if (tid < 133) {
            float k3 = knew(s_tmp); s_k[3][tid] = k3;
            float v = s_y[tid] + h * (A51 * s_k[0][tid] + A52 * s_k[1][tid]
                                    + A53 * s_k[2][tid] + A54 * k3);
            s_tmp[tid] = v;
            if (tid >= 5) s_xbr[tid - 4] = rep_bf(v);
        }
        if (tid == 256) set_t(tt + C5 * h);
        __syncthreads();

        vf(s_tmp);
        if (tid < 133) {
            float k4 = knew(s_tmp); s_k[4][tid] = k4;
            float v = s_y[tid] + h * (A61 * s_k[0][tid] + A62 * s_k[1][tid]
                                    + A63 * s_k[2][tid] + A64 * s_k[3][tid] + A65 * k4);
            s_tmp[tid] = v;
            if (tid >= 5) s_xbr[tid - 4] = rep_bf(v);
        }
        if (tid == 256) set_t(tt + h);
        __syncthreads();

        vf(s_tmp);
        if (tid < 133) {
            float k5 = knew(s_tmp);
            float v = s_y[tid] + h * (B1 * s_k[0][tid] + B2 * s_k[1][tid]
                                    + B3 * s_k[2][tid] + B4 * s_k[3][tid]
                                    + B5 * s_k[4][tid] + B6 * k5);
            s_y[tid] = v;
            if (tid >= 5) s_xbr[tid - 4] = rep_bf(v);
        }
        if (tid == 256) set_t(t_after);
        __syncthreads();
    };

    float t0v = 0.f;
    for (int s = 0; s < 64; ++s) {
        float tn = ts[b * 64 + s];
        float dt = (tn - t0v) * 0.5f;    // K_SUB = 2
        tsit5(t0v,      dt, t0v + dt);
        tsit5(t0v + dt, dt, tn);
        t0v = tn;
        if (tid < 5)   out[(b * 64 + s) * 5 + tid] = s_y[tid];
        if (tid < 128) out[OFF_H + (b * 64 + s) * 128 + tid] = s_y[5 + tid];
    }
}

extern "C" void kernel_launch(void* const* d_in, const int* in_sizes, int n_in,
                              void* d_out, int out_size) {
    const float* ts      = (const float*)d_in[0];
    const float* ys      = (const float*)d_in[1];
    const float* scale   = (const float*)d_in[2];
    const float* mlp_w0  = (const float*)d_in[3];
    const float* mlp_b0  = (const float*)d_in[4];
    const float* mlp_w1  = (const float*)d_in[5];
    const float* mlp_b1  = (const float*)d_in[6];
    const float* mlp_w2  = (const float*)d_in[7];
    const float* mlp_b2  = (const float*)d_in[8];
    const float* gru_wih = (const float*)d_in[9];
    const float* gru_whh = (const float*)d_in[10];
    const float* gru_b   = (const float*)d_in[11];
    const float* gru_bn  = (const float*)d_in[12];
    const float* htl_w   = (const float*)d_in[13];
    const float* htl_b   = (const float*)d_in[14];
    const float* htb_w   = (const float*)d_in[15];
    const float* htb_b   = (const float*)d_in[16];
    const float* lti_w   = (const float*)d_in[17];
    const float* lti_b   = (const float*)d_in[18];
    const float* lth_w   = (const float*)d_in[19];
    const float* lth_b   = (const float*)d_in[20];

    static int attr_set = 0;
    if (!attr_set) {
        cudaFuncSetAttribute(solve_kernel,
                             cudaFuncAttributeMaxDynamicSharedMemorySize,
                             DYN_SMEM_BYTES);
        attr_set = 1;
    }

    prep_kernel<<<96, 256>>>(mlp_w0, mlp_w1, mlp_w2, gru_wih, gru_whh);
    solve_kernel<<<64, 512, DYN_SMEM_BYTES>>>(ts, ys, scale, mlp_b0, mlp_b1, mlp_b2,
                              gru_b, gru_bn, htl_w, htl_b, htb_w, htb_b,
                              lti_w, lti_b, lth_w, lth_b, (float*)d_out);
}